// round 1
// baseline (speedup 1.0000x reference)
#include <cuda_runtime.h>

// ---------------- problem constants (fixed by setup_inputs) ----------------
#define S_LEN 4096
#define B_SZ  2
#define NROWS (B_SZ * S_LEN)          // 8192 token rows
#define D_IN  7168
#define LORA  1536
#define NH    64
#define DHD   128
#define HALF  32                      // DR/2
#define QN    (NROWS * NH * DHD)      // 67108864
#define WN    (NROWS * NH)            // 524288
#define KN    (NROWS * DHD)           // 1048576

#define WSCALE 0.011048543456039806f  // H^-0.5 * DH^-0.5 = 8192^-0.5
#define HSCALE 0.08838834764831845f   // 128^-0.5

// scratch: pre-norm k projection (8192 x 128 fp32 = 4 MB)
__device__ float g_kpre[NROWS * DHD];

// =====================================================================
// SGEMM (NT): C[M,N] = A[M,K] * B[N,K]^T.  BM=BN=128, BK=16, 256 thr,
// 8x8 per-thread tile, register prefetch of next k-tile.
// All of M,N,K are multiples of the tile here (8192,8192,1536).
// =====================================================================
__global__ __launch_bounds__(256, 2)
void sgemm_q(const float* __restrict__ A, const float* __restrict__ B,
             float* __restrict__ C, int M, int N, int K)
{
    __shared__ float As[16][128];
    __shared__ float Bs[16][128];
    const int bm = blockIdx.y << 7, bn = blockIdx.x << 7;
    const int tid = threadIdx.x;
    const int lr = tid >> 2;          // 0..63
    const int lc = (tid & 3) << 2;    // 0,4,8,12
    const int tm = (tid >> 4) << 3;
    const int tn = (tid & 15) << 3;

    const float* Ap0 = A + (size_t)(bm + lr) * K + lc;
    const float* Ap1 = Ap0 + (size_t)64 * K;
    const float* Bp0 = B + (size_t)(bn + lr) * K + lc;
    const float* Bp1 = Bp0 + (size_t)64 * K;

    float4 ra0 = *(const float4*)Ap0;
    float4 ra1 = *(const float4*)Ap1;
    float4 rb0 = *(const float4*)Bp0;
    float4 rb1 = *(const float4*)Bp1;

    float acc[8][8] = {};

    for (int kt = 0; kt < K; kt += 16) {
        __syncthreads();
        As[lc+0][lr   ]=ra0.x; As[lc+1][lr   ]=ra0.y; As[lc+2][lr   ]=ra0.z; As[lc+3][lr   ]=ra0.w;
        As[lc+0][lr+64]=ra1.x; As[lc+1][lr+64]=ra1.y; As[lc+2][lr+64]=ra1.z; As[lc+3][lr+64]=ra1.w;
        Bs[lc+0][lr   ]=rb0.x; Bs[lc+1][lr   ]=rb0.y; Bs[lc+2][lr   ]=rb0.z; Bs[lc+3][lr   ]=rb0.w;
        Bs[lc+0][lr+64]=rb1.x; Bs[lc+1][lr+64]=rb1.y; Bs[lc+2][lr+64]=rb1.z; Bs[lc+3][lr+64]=rb1.w;
        __syncthreads();

        if (kt + 16 < K) {
            ra0 = *(const float4*)(Ap0 + kt + 16);
            ra1 = *(const float4*)(Ap1 + kt + 16);
            rb0 = *(const float4*)(Bp0 + kt + 16);
            rb1 = *(const float4*)(Bp1 + kt + 16);
        }

        #pragma unroll
        for (int k = 0; k < 16; k++) {
            float a[8], b[8];
            *(float4*)&a[0] = *(const float4*)&As[k][tm];
            *(float4*)&a[4] = *(const float4*)&As[k][tm + 4];
            *(float4*)&b[0] = *(const float4*)&Bs[k][tn];
            *(float4*)&b[4] = *(const float4*)&Bs[k][tn + 4];
            #pragma unroll
            for (int i = 0; i < 8; i++)
                #pragma unroll
                for (int j = 0; j < 8; j++)
                    acc[i][j] += a[i] * b[j];
        }
    }

    #pragma unroll
    for (int i = 0; i < 8; i++) {
        float* cp = C + (size_t)(bm + tm + i) * N + bn + tn;
        *(float4*)cp       = make_float4(acc[i][0], acc[i][1], acc[i][2], acc[i][3]);
        *(float4*)(cp + 4) = make_float4(acc[i][4], acc[i][5], acc[i][6], acc[i][7]);
    }
}

// =====================================================================
// Projection GEMM: reads x once, computes both k_pre (N-cols 0..127 from
// wk_w) and weights (N-cols 128..191 from weights_proj_w, scaled).
// Logical N = 192, grid.x = 2 tiles of 128 (cols 192..255 padded).
// =====================================================================
__global__ __launch_bounds__(256, 2)
void sgemm_proj(const float* __restrict__ A, const float* __restrict__ Wk,
                const float* __restrict__ Wp, float* __restrict__ wout, int K)
{
    __shared__ float As[16][128];
    __shared__ float Bs[16][128];
    const int bm = blockIdx.y << 7, bn = blockIdx.x << 7;
    const int tid = threadIdx.x;
    const int lr = tid >> 2;
    const int lc = (tid & 3) << 2;
    const int tm = (tid >> 4) << 3;
    const int tn = (tid & 15) << 3;

    const float* Ap0 = A + (size_t)(bm + lr) * K + lc;
    const float* Ap1 = Ap0 + (size_t)64 * K;

    const int n0 = bn + lr, n1 = bn + lr + 64;
    const float* Bp0 = (n0 < 128) ? (Wk + (size_t)n0 * K + lc)
                    : (n0 < 192) ? (Wp + (size_t)(n0 - 128) * K + lc) : 0;
    const float* Bp1 = (n1 < 128) ? (Wk + (size_t)n1 * K + lc)
                    : (n1 < 192) ? (Wp + (size_t)(n1 - 128) * K + lc) : 0;

    float4 ra0 = *(const float4*)Ap0;
    float4 ra1 = *(const float4*)Ap1;
    float4 rb0 = Bp0 ? *(const float4*)Bp0 : make_float4(0.f,0.f,0.f,0.f);
    float4 rb1 = Bp1 ? *(const float4*)Bp1 : make_float4(0.f,0.f,0.f,0.f);

    float acc[8][8] = {};

    for (int kt = 0; kt < K; kt += 16) {
        __syncthreads();
        As[lc+0][lr   ]=ra0.x; As[lc+1][lr   ]=ra0.y; As[lc+2][lr   ]=ra0.z; As[lc+3][lr   ]=ra0.w;
        As[lc+0][lr+64]=ra1.x; As[lc+1][lr+64]=ra1.y; As[lc+2][lr+64]=ra1.z; As[lc+3][lr+64]=ra1.w;
        Bs[lc+0][lr   ]=rb0.x; Bs[lc+1][lr   ]=rb0.y; Bs[lc+2][lr   ]=rb0.z; Bs[lc+3][lr   ]=rb0.w;
        Bs[lc+0][lr+64]=rb1.x; Bs[lc+1][lr+64]=rb1.y; Bs[lc+2][lr+64]=rb1.z; Bs[lc+3][lr+64]=rb1.w;
        __syncthreads();

        if (kt + 16 < K) {
            ra0 = *(const float4*)(Ap0 + kt + 16);
            ra1 = *(const float4*)(Ap1 + kt + 16);
            if (Bp0) rb0 = *(const float4*)(Bp0 + kt + 16);
            if (Bp1) rb1 = *(const float4*)(Bp1 + kt + 16);
        }

        #pragma unroll
        for (int k = 0; k < 16; k++) {
            float a[8], b[8];
            *(float4*)&a[0] = *(const float4*)&As[k][tm];
            *(float4*)&a[4] = *(const float4*)&As[k][tm + 4];
            *(float4*)&b[0] = *(const float4*)&Bs[k][tn];
            *(float4*)&b[4] = *(const float4*)&Bs[k][tn + 4];
            #pragma unroll
            for (int i = 0; i < 8; i++)
                #pragma unroll
                for (int j = 0; j < 8; j++)
                    acc[i][j] += a[i] * b[j];
        }
    }

    #pragma unroll
    for (int i = 0; i < 8; i++) {
        const int m = bm + tm + i;
        #pragma unroll
        for (int j = 0; j < 8; j++) {
            const int n = bn + tn + j;
            if (n < 128)      g_kpre[(size_t)m * DHD + n] = acc[i][j];
            else if (n < 192) wout[(size_t)m * NH + (n - 128)] = acc[i][j] * WSCALE;
        }
    }
}

// =====================================================================
// q epilogue (in place): per (row, head) 128-vector -> RoPE on dims 0..63
// (pairs (i, i+32)), then FWHT (== @ Hmat, Sylvester order), scale 128^-0.5.
// One warp handles a head; lane owns dh = {lane, lane+32, lane+64, lane+96}.
// =====================================================================
__global__ void q_epilogue(float* __restrict__ q,
                           const float* __restrict__ fc, const float* __restrict__ fs)
{
    const int row  = blockIdx.x;
    const int warp = threadIdx.x >> 5, lane = threadIdx.x & 31;
    const int pos  = row & (S_LEN - 1);
    const float c = fc[pos * HALF + lane];
    const float s = fs[pos * HALF + lane];

    for (int h = warp; h < NH; h += 8) {
        float* base = q + (size_t)row * (NH * DHD) + (size_t)h * DHD;
        float v0 = base[lane], v1 = base[lane + 32], v2 = base[lane + 64], v3 = base[lane + 96];
        // RoPE (non-interleaved): dims [0,32) x [32,64)
        float x1 = v0, x2 = v1;
        v0 = x1 * c - x2 * s;
        v1 = x1 * s + x2 * c;
        // FWHT: cross-lane stages (stride 1..16)
        #pragma unroll
        for (int st = 1; st < 32; st <<= 1) {
            float p0 = __shfl_xor_sync(0xffffffffu, v0, st);
            float p1 = __shfl_xor_sync(0xffffffffu, v1, st);
            float p2 = __shfl_xor_sync(0xffffffffu, v2, st);
            float p3 = __shfl_xor_sync(0xffffffffu, v3, st);
            if (lane & st) { v0 = p0 - v0; v1 = p1 - v1; v2 = p2 - v2; v3 = p3 - v3; }
            else           { v0 += p0;     v1 += p1;     v2 += p2;     v3 += p3;     }
        }
        // in-thread stages (stride 32, 64)
        float t0 = v0 + v1, t1 = v0 - v1, t2 = v2 + v3, t3 = v2 - v3;
        v0 = t0 + t2; v2 = t0 - t2; v1 = t1 + t3; v3 = t1 - t3;
        base[lane]      = v0 * HSCALE;
        base[lane + 32] = v1 * HSCALE;
        base[lane + 64] = v2 * HSCALE;
        base[lane + 96] = v3 * HSCALE;
    }
}

// =====================================================================
// k epilogue: layernorm over 128, RoPE, FWHT, scale. One warp per row.
// =====================================================================
__global__ void k_epilogue(float* __restrict__ kout,
                           const float* __restrict__ fc, const float* __restrict__ fs,
                           const float* __restrict__ g, const float* __restrict__ bta)
{
    const int warp = threadIdx.x >> 5, lane = threadIdx.x & 31;
    const int row  = blockIdx.x * 8 + warp;
    const int pos  = row & (S_LEN - 1);
    const float* base = g_kpre + (size_t)row * DHD;

    float v0 = base[lane], v1 = base[lane + 32], v2 = base[lane + 64], v3 = base[lane + 96];

    float sum = v0 + v1 + v2 + v3;
    float sq  = v0*v0 + v1*v1 + v2*v2 + v3*v3;
    #pragma unroll
    for (int o = 16; o; o >>= 1) {
        sum += __shfl_xor_sync(0xffffffffu, sum, o);
        sq  += __shfl_xor_sync(0xffffffffu, sq,  o);
    }
    const float mu  = sum * (1.f / 128.f);
    const float var = sq * (1.f / 128.f) - mu * mu;
    const float r   = rsqrtf(var + 1e-5f);

    v0 = (v0 - mu) * r * g[lane]      + bta[lane];
    v1 = (v1 - mu) * r * g[lane + 32] + bta[lane + 32];
    v2 = (v2 - mu) * r * g[lane + 64] + bta[lane + 64];
    v3 = (v3 - mu) * r * g[lane + 96] + bta[lane + 96];

    const float c = fc[pos * HALF + lane];
    const float s = fs[pos * HALF + lane];
    float x1 = v0, x2 = v1;
    v0 = x1 * c - x2 * s;
    v1 = x1 * s + x2 * c;

    #pragma unroll
    for (int st = 1; st < 32; st <<= 1) {
        float p0 = __shfl_xor_sync(0xffffffffu, v0, st);
        float p1 = __shfl_xor_sync(0xffffffffu, v1, st);
        float p2 = __shfl_xor_sync(0xffffffffu, v2, st);
        float p3 = __shfl_xor_sync(0xffffffffu, v3, st);
        if (lane & st) { v0 = p0 - v0; v1 = p1 - v1; v2 = p2 - v2; v3 = p3 - v3; }
        else           { v0 += p0;     v1 += p1;     v2 += p2;     v3 += p3;     }
    }
    float t0 = v0 + v1, t1 = v0 - v1, t2 = v2 + v3, t3 = v2 - v3;
    v0 = t0 + t2; v2 = t0 - t2; v1 = t1 + t3; v3 = t1 - t3;

    float* ob = kout + (size_t)row * DHD;
    ob[lane]      = v0 * HSCALE;
    ob[lane + 32] = v1 * HSCALE;
    ob[lane + 64] = v2 * HSCALE;
    ob[lane + 96] = v3 * HSCALE;
}

__global__ void write_end(float* __restrict__ eout, const int* __restrict__ sp)
{
    *eout = (float)(*sp + S_LEN);
}

// =====================================================================
extern "C" void kernel_launch(void* const* d_in, const int* in_sizes, int n_in,
                              void* d_out, int out_size)
{
    const float* x   = (const float*)d_in[0];
    const float* qr  = (const float*)d_in[1];
    const float* fc  = (const float*)d_in[2];
    const float* fs  = (const float*)d_in[3];
    const float* wqb = (const float*)d_in[4];
    const float* wk  = (const float*)d_in[5];
    const float* kg  = (const float*)d_in[6];
    const float* kb  = (const float*)d_in[7];
    const float* wp  = (const float*)d_in[8];
    const int*   sp  = (const int*)d_in[9];

    float* out  = (float*)d_out;
    float* qout = out;
    float* wout = out + QN;
    float* kout = out + QN + WN;
    float* eout = out + QN + WN + KN;

    // q = qr @ wq_b^T written directly into the q output region
    dim3 g1(64, 64);
    sgemm_q<<<g1, 256>>>(qr, wqb, qout, NROWS, NH * DHD, LORA);

    // k_pre + weights from x (single pass over x)
    dim3 g2(2, 64);
    sgemm_proj<<<g2, 256>>>(x, wk, wp, wout, D_IN);

    // epilogues
    q_epilogue<<<NROWS, 256>>>(qout, fc, fs);
    k_epilogue<<<NROWS / 8, 256>>>(kout, fc, fs, kg, kb);
    write_end<<<1, 1>>>(eout, sp);
}

// round 2
// speedup vs baseline: 2.6284x; 2.6284x over previous
#include <cuda_runtime.h>
#include <cuda_bf16.h>
#include <cstdint>

// ---------------- problem constants ----------------
#define S_LEN 4096
#define NROWS 8192
#define D_IN  7168
#define LORA  1536
#define NH    64
#define DHD   128
#define HALF  32
#define QN    (NROWS * NH * DHD)
#define WN    (NROWS * NH)
#define KN    (NROWS * DHD)

#define WSCALE 0.011048543456039806f  // (H*DH)^-0.5
#define HSCALE 0.08838834764831845f   // 128^-0.5

// ---------------- device scratch ----------------
__device__ __nv_bfloat16 g_qr_h[NROWS * LORA];
__device__ __nv_bfloat16 g_qr_l[NROWS * LORA];
__device__ __nv_bfloat16 g_wq_h[NROWS * LORA];
__device__ __nv_bfloat16 g_wq_l[NROWS * LORA];
__device__ __nv_bfloat16 g_x_h[(size_t)NROWS * D_IN];
__device__ __nv_bfloat16 g_x_l[(size_t)NROWS * D_IN];
__device__ __nv_bfloat16 g_wb_h[256 * D_IN];
__device__ __nv_bfloat16 g_wb_l[256 * D_IN];
__device__ float g_kpre[NROWS * DHD];

// ---------------- helpers ----------------
__device__ __forceinline__ uint32_t pack_bf2(__nv_bfloat16 a, __nv_bfloat16 b) {
    return (uint32_t)__bfloat16_as_ushort(a) | ((uint32_t)__bfloat16_as_ushort(b) << 16);
}

__device__ __forceinline__ void split4(float4 v, uint2& hi, uint2& lo) {
    __nv_bfloat16 hx = __float2bfloat16_rn(v.x);
    __nv_bfloat16 hy = __float2bfloat16_rn(v.y);
    __nv_bfloat16 hz = __float2bfloat16_rn(v.z);
    __nv_bfloat16 hw = __float2bfloat16_rn(v.w);
    __nv_bfloat16 lx = __float2bfloat16_rn(v.x - __bfloat162float(hx));
    __nv_bfloat16 ly = __float2bfloat16_rn(v.y - __bfloat162float(hy));
    __nv_bfloat16 lz = __float2bfloat16_rn(v.z - __bfloat162float(hz));
    __nv_bfloat16 lw = __float2bfloat16_rn(v.w - __bfloat162float(hw));
    hi = make_uint2(pack_bf2(hx, hy), pack_bf2(hz, hw));
    lo = make_uint2(pack_bf2(lx, ly), pack_bf2(lz, lw));
}

__global__ void split_bf16(const float4* __restrict__ src,
                           uint2* __restrict__ hi, uint2* __restrict__ lo, int n4)
{
    int i = blockIdx.x * blockDim.x + threadIdx.x;
    if (i >= n4) return;
    uint2 h, l;
    split4(src[i], h, l);
    hi[i] = h;
    lo[i] = l;
}

// combined proj weight matrix: rows 0-127 = wk, 128-191 = wp*WSCALE, 192-255 = 0
__global__ void build_wb(const float* __restrict__ wk, const float* __restrict__ wp)
{
    int i = blockIdx.x * blockDim.x + threadIdx.x;
    const int total = 256 * D_IN / 4;
    if (i >= total) return;
    int row = i / (D_IN / 4);
    int c4  = i % (D_IN / 4);
    float4 v;
    if (row < 128)      v = ((const float4*)wk)[row * (D_IN / 4) + c4];
    else if (row < 192) {
        v = ((const float4*)wp)[(row - 128) * (D_IN / 4) + c4];
        v.x *= WSCALE; v.y *= WSCALE; v.z *= WSCALE; v.w *= WSCALE;
    } else v = make_float4(0.f, 0.f, 0.f, 0.f);
    uint2 h, l;
    split4(v, h, l);
    ((uint2*)g_wb_h)[i] = h;
    ((uint2*)g_wb_l)[i] = l;
}

// ---------------- PTX wrappers ----------------
#define LDSM4(r0, r1, r2, r3, addr)                                              \
    asm volatile("ldmatrix.sync.aligned.m8n8.x4.shared.b16 {%0,%1,%2,%3},[%4];"  \
                 : "=r"(r0), "=r"(r1), "=r"(r2), "=r"(r3) : "r"(addr))

#define MMA_BF16(d, a, b)                                                        \
    asm volatile("mma.sync.aligned.m16n8k16.row.col.f32.bf16.bf16.f32 "          \
                 "{%0,%1,%2,%3},{%4,%5,%6,%7},{%8,%9},{%0,%1,%2,%3};"            \
                 : "+f"((d)[0]), "+f"((d)[1]), "+f"((d)[2]), "+f"((d)[3])        \
                 : "r"((a)[0]), "r"((a)[1]), "r"((a)[2]), "r"((a)[3]),           \
                   "r"((b)[0]), "r"((b)[1]))

#define CP_ASYNC16(dst, src)                                                     \
    asm volatile("cp.async.cg.shared.global [%0], [%1], 16;\n" :: "r"(dst), "l"(src))
#define CP_COMMIT()  asm volatile("cp.async.commit_group;\n" ::: "memory")
#define CP_WAIT1()   asm volatile("cp.async.wait_group 1;\n" ::: "memory")

// =====================================================================
// bf16x3 MMA GEMM (NT): C[M,N] += (Ah+Al)[M,K] * (Bh+Bl)[N,K]^T
// Block 128x128x32, 256 threads, warp grid 2(M)x4(N), warp tile 64x32.
// smem: padded rows of 40 bf16 (80B) -> conflict-free ldmatrix (5r mod 8).
// 2-stage cp.async pipeline.
// MODE 0: store C[m][8192] directly (q GEMM)
// MODE 1: cols 0-127 -> g_kpre, 128-191 -> Wout (weights), rest dropped
// =====================================================================
template<int MODE>
__global__ __launch_bounds__(256, 2)
void mma_gemm(const __nv_bfloat16* __restrict__ Ah, const __nv_bfloat16* __restrict__ Al,
              const __nv_bfloat16* __restrict__ Bh, const __nv_bfloat16* __restrict__ Bl,
              float* __restrict__ C, float* __restrict__ Wout, int K)
{
    extern __shared__ char smem_raw[];
    const uint32_t smem = (uint32_t)__cvta_generic_to_shared(smem_raw);
    constexpr int STAGE = 40960;              // bytes per stage
    constexpr int AHOF = 0, ALOF = 10240, BHOF = 20480, BLOF = 30720;

    const int tid = threadIdx.x, lane = tid & 31, warp = tid >> 5;
    const int wm = warp >> 2, wn = warp & 3;
    const int bm = blockIdx.y << 7, bn = blockIdx.x << 7;
    const int niter = K >> 5;

    float acc[4][4][4] = {};

    // ---- cp.async issue of k-chunk `it` into stage buffer `buf` ----
    auto issue = [&](int it, int buf) {
        const int kt = it << 5;
        #pragma unroll
        for (int t = 0; t < 8; t++) {
            int cid = tid + (t << 8);          // 0..2047
            int arr = cid >> 9;                // 0:Ah 1:Al 2:Bh 3:Bl
            int row = (cid >> 2) & 127;
            int c   = cid & 3;
            const __nv_bfloat16* g;
            int r0;
            if (arr == 0)      { g = Ah; r0 = bm + row; }
            else if (arr == 1) { g = Al; r0 = bm + row; }
            else if (arr == 2) { g = Bh; r0 = bn + row; }
            else               { g = Bl; r0 = bn + row; }
            uint32_t dst = smem + buf * STAGE + arr * 10240 + row * 80 + c * 16;
            const void* src = g + (size_t)r0 * K + kt + c * 8;
            CP_ASYNC16(dst, src);
        }
        CP_COMMIT();
    };

    issue(0, 0);
    if (niter > 1) issue(1, 1); else CP_COMMIT();

    for (int it = 0; it < niter; ++it) {
        CP_WAIT1();
        __syncthreads();

        const uint32_t sb = smem + (it & 1) * STAGE;
        #pragma unroll
        for (int s = 0; s < 2; s++) {
            // B fragments (hi and lo): two x4 cover 4 n-tiles each
            uint32_t bh[4][2], bl[4][2];
            {
                const int g = lane >> 3;
                #pragma unroll
                for (int p = 0; p < 2; p++) {
                    int row = (wn << 5) + (((p << 1) + (g >> 1)) << 3) + (lane & 7);
                    uint32_t ad = sb + BHOF + row * 80 + (s << 5) + ((g & 1) << 4);
                    LDSM4(bh[2*p][0], bh[2*p][1], bh[2*p+1][0], bh[2*p+1][1], ad);
                    uint32_t ad2 = ad + (BLOF - BHOF);
                    LDSM4(bl[2*p][0], bl[2*p][1], bl[2*p+1][0], bl[2*p+1][1], ad2);
                }
            }
            // A hi fragments
            uint32_t a[4][4];
            #pragma unroll
            for (int i = 0; i < 4; i++) {
                int row = (wm << 6) + (i << 4) + (lane & 15);
                uint32_t ad = sb + AHOF + row * 80 + ((lane >> 4) << 4) + (s << 5);
                LDSM4(a[i][0], a[i][1], a[i][2], a[i][3], ad);
            }
            #pragma unroll
            for (int i = 0; i < 4; i++)
                #pragma unroll
                for (int j = 0; j < 4; j++) {
                    MMA_BF16(acc[i][j], a[i], bh[j]);
                    MMA_BF16(acc[i][j], a[i], bl[j]);
                }
            // A lo fragments (reuse regs)
            #pragma unroll
            for (int i = 0; i < 4; i++) {
                int row = (wm << 6) + (i << 4) + (lane & 15);
                uint32_t ad = sb + ALOF + row * 80 + ((lane >> 4) << 4) + (s << 5);
                LDSM4(a[i][0], a[i][1], a[i][2], a[i][3], ad);
            }
            #pragma unroll
            for (int i = 0; i < 4; i++)
                #pragma unroll
                for (int j = 0; j < 4; j++)
                    MMA_BF16(acc[i][j], a[i], bh[j]);
        }

        __syncthreads();
        if (it + 2 < niter) issue(it + 2, it & 1);
        else CP_COMMIT();
    }

    // ---- epilogue store ----
    #pragma unroll
    for (int i = 0; i < 4; i++) {
        #pragma unroll
        for (int j = 0; j < 4; j++) {
            const int gm = bm + (wm << 6) + (i << 4) + (lane >> 2);
            const int gn = bn + (wn << 5) + (j << 3) + ((lane & 3) << 1);
            if (MODE == 0) {
                *(float2*)(C + (size_t)gm * 8192 + gn)       = make_float2(acc[i][j][0], acc[i][j][1]);
                *(float2*)(C + (size_t)(gm + 8) * 8192 + gn) = make_float2(acc[i][j][2], acc[i][j][3]);
            } else {
                #pragma unroll
                for (int rr = 0; rr < 2; rr++) {
                    const int m = gm + rr * 8;
                    #pragma unroll
                    for (int cc = 0; cc < 2; cc++) {
                        const int n = gn + cc;
                        const float v = acc[i][j][rr * 2 + cc];
                        if (n < 128)      g_kpre[(size_t)m * DHD + n] = v;
                        else if (n < 192) Wout[(size_t)m * NH + (n - 128)] = v;
                    }
                }
            }
        }
    }
}

// =====================================================================
// q epilogue (in place): RoPE (pairs (i, i+32)) + FWHT (@Hmat) + scale.
// =====================================================================
__global__ void q_epilogue(float* __restrict__ q,
                           const float* __restrict__ fc, const float* __restrict__ fs)
{
    const int row  = blockIdx.x;
    const int warp = threadIdx.x >> 5, lane = threadIdx.x & 31;
    const int pos  = row & (S_LEN - 1);
    const float c = fc[pos * HALF + lane];
    const float s = fs[pos * HALF + lane];

    for (int h = warp; h < NH; h += 8) {
        float* base = q + (size_t)row * (NH * DHD) + (size_t)h * DHD;
        float v0 = base[lane], v1 = base[lane + 32], v2 = base[lane + 64], v3 = base[lane + 96];
        float x1 = v0, x2 = v1;
        v0 = x1 * c - x2 * s;
        v1 = x1 * s + x2 * c;
        #pragma unroll
        for (int st = 1; st < 32; st <<= 1) {
            float p0 = __shfl_xor_sync(0xffffffffu, v0, st);
            float p1 = __shfl_xor_sync(0xffffffffu, v1, st);
            float p2 = __shfl_xor_sync(0xffffffffu, v2, st);
            float p3 = __shfl_xor_sync(0xffffffffu, v3, st);
            if (lane & st) { v0 = p0 - v0; v1 = p1 - v1; v2 = p2 - v2; v3 = p3 - v3; }
            else           { v0 += p0;     v1 += p1;     v2 += p2;     v3 += p3;     }
        }
        float t0 = v0 + v1, t1 = v0 - v1, t2 = v2 + v3, t3 = v2 - v3;
        v0 = t0 + t2; v2 = t0 - t2; v1 = t1 + t3; v3 = t1 - t3;
        base[lane]      = v0 * HSCALE;
        base[lane + 32] = v1 * HSCALE;
        base[lane + 64] = v2 * HSCALE;
        base[lane + 96] = v3 * HSCALE;
    }
}

// =====================================================================
// k epilogue: layernorm(128) + RoPE + FWHT + scale. One warp per row.
// =====================================================================
__global__ void k_epilogue(float* __restrict__ kout,
                           const float* __restrict__ fc, const float* __restrict__ fs,
                           const float* __restrict__ g, const float* __restrict__ bta)
{
    const int warp = threadIdx.x >> 5, lane = threadIdx.x & 31;
    const int row  = blockIdx.x * 8 + warp;
    const int pos  = row & (S_LEN - 1);
    const float* base = g_kpre + (size_t)row * DHD;

    float v0 = base[lane], v1 = base[lane + 32], v2 = base[lane + 64], v3 = base[lane + 96];

    float sum = v0 + v1 + v2 + v3;
    float sq  = v0*v0 + v1*v1 + v2*v2 + v3*v3;
    #pragma unroll
    for (int o = 16; o; o >>= 1) {
        sum += __shfl_xor_sync(0xffffffffu, sum, o);
        sq  += __shfl_xor_sync(0xffffffffu, sq,  o);
    }
    const float mu  = sum * (1.f / 128.f);
    const float var = sq * (1.f / 128.f) - mu * mu;
    const float r   = rsqrtf(var + 1e-5f);

    v0 = (v0 - mu) * r * g[lane]      + bta[lane];
    v1 = (v1 - mu) * r * g[lane + 32] + bta[lane + 32];
    v2 = (v2 - mu) * r * g[lane + 64] + bta[lane + 64];
    v3 = (v3 - mu) * r * g[lane + 96] + bta[lane + 96];

    const float c = fc[pos * HALF + lane];
    const float s = fs[pos * HALF + lane];
    float x1 = v0, x2 = v1;
    v0 = x1 * c - x2 * s;
    v1 = x1 * s + x2 * c;

    #pragma unroll
    for (int st = 1; st < 32; st <<= 1) {
        float p0 = __shfl_xor_sync(0xffffffffu, v0, st);
        float p1 = __shfl_xor_sync(0xffffffffu, v1, st);
        float p2 = __shfl_xor_sync(0xffffffffu, v2, st);
        float p3 = __shfl_xor_sync(0xffffffffu, v3, st);
        if (lane & st) { v0 = p0 - v0; v1 = p1 - v1; v2 = p2 - v2; v3 = p3 - v3; }
        else           { v0 += p0;     v1 += p1;     v2 += p2;     v3 += p3;     }
    }
    float t0 = v0 + v1, t1 = v0 - v1, t2 = v2 + v3, t3 = v2 - v3;
    v0 = t0 + t2; v2 = t0 - t2; v1 = t1 + t3; v3 = t1 - t3;

    float* ob = kout + (size_t)row * DHD;
    ob[lane]      = v0 * HSCALE;
    ob[lane + 32] = v1 * HSCALE;
    ob[lane + 64] = v2 * HSCALE;
    ob[lane + 96] = v3 * HSCALE;
}

__global__ void write_end(float* __restrict__ eout, const int* __restrict__ sp)
{
    *eout = (float)(*sp + S_LEN);
}

// =====================================================================
extern "C" void kernel_launch(void* const* d_in, const int* in_sizes, int n_in,
                              void* d_out, int out_size)
{
    const float* x   = (const float*)d_in[0];
    const float* qr  = (const float*)d_in[1];
    const float* fc  = (const float*)d_in[2];
    const float* fs  = (const float*)d_in[3];
    const float* wqb = (const float*)d_in[4];
    const float* wk  = (const float*)d_in[5];
    const float* kg  = (const float*)d_in[6];
    const float* kb  = (const float*)d_in[7];
    const float* wp  = (const float*)d_in[8];
    const int*   sp  = (const int*)d_in[9];

    float* out  = (float*)d_out;
    float* qout = out;
    float* wout = out + QN;
    float* kout = out + QN + WN;
    float* eout = out + QN + WN + KN;

    void *qrh, *qrl, *wqh, *wql, *xh, *xl;
    cudaGetSymbolAddress(&qrh, g_qr_h);
    cudaGetSymbolAddress(&qrl, g_qr_l);
    cudaGetSymbolAddress(&wqh, g_wq_h);
    cudaGetSymbolAddress(&wql, g_wq_l);
    cudaGetSymbolAddress(&xh,  g_x_h);
    cudaGetSymbolAddress(&xl,  g_x_l);

    cudaFuncSetAttribute(mma_gemm<0>, cudaFuncAttributeMaxDynamicSharedMemorySize, 81920);
    cudaFuncSetAttribute(mma_gemm<1>, cudaFuncAttributeMaxDynamicSharedMemorySize, 81920);

    // ---- splits ----
    const int n4q = NROWS * LORA / 4;
    split_bf16<<<(n4q + 255) / 256, 256>>>((const float4*)qr,  (uint2*)qrh, (uint2*)qrl, n4q);
    split_bf16<<<(n4q + 255) / 256, 256>>>((const float4*)wqb, (uint2*)wqh, (uint2*)wql, n4q);
    const int n4x = NROWS * D_IN / 4;
    split_bf16<<<(n4x + 255) / 256, 256>>>((const float4*)x,   (uint2*)xh,  (uint2*)xl,  n4x);
    const int n4b = 256 * D_IN / 4;
    build_wb<<<(n4b + 255) / 256, 256>>>(wk, wp);

    // ---- GEMMs on tensor cores ----
    void *wbh, *wbl;
    cudaGetSymbolAddress(&wbh, g_wb_h);
    cudaGetSymbolAddress(&wbl, g_wb_l);

    mma_gemm<0><<<dim3(64, 64), 256, 81920>>>(
        (const __nv_bfloat16*)qrh, (const __nv_bfloat16*)qrl,
        (const __nv_bfloat16*)wqh, (const __nv_bfloat16*)wql,
        qout, nullptr, LORA);

    mma_gemm<1><<<dim3(2, 64), 256, 81920>>>(
        (const __nv_bfloat16*)xh, (const __nv_bfloat16*)xl,
        (const __nv_bfloat16*)wbh, (const __nv_bfloat16*)wbl,
        nullptr, wout, D_IN);

    // ---- epilogues ----
    q_epilogue<<<NROWS, 256>>>(qout, fc, fs);
    k_epilogue<<<NROWS / 8, 256>>>(kout, fc, fs, kg, kb);
    write_end<<<1, 1>>>(eout, sp);
}

// round 4
// speedup vs baseline: 3.1092x; 1.1829x over previous
#include <cuda_runtime.h>
#include <cuda_bf16.h>
#include <cuda.h>
#include <cstdint>

// ---------------- problem constants ----------------
#define S_LEN 4096
#define NROWS 8192
#define D_IN  7168
#define LORA  1536
#define NH    64
#define DHD   128
#define QN    (NROWS * NH * DHD)
#define WN    (NROWS * NH)
#define KN    (NROWS * DHD)

#define WSCALE 0.011048543456039806f  // (H*DH)^-0.5
#define HSCALE 0.08838834764831845f   // 128^-0.5

// ---------------- device scratch (bf16 hi/lo splits) ----------------
__device__ __nv_bfloat16 g_qr_h[NROWS * LORA];
__device__ __nv_bfloat16 g_qr_l[NROWS * LORA];
__device__ __nv_bfloat16 g_wq_h[NROWS * LORA];
__device__ __nv_bfloat16 g_wq_l[NROWS * LORA];
__device__ __nv_bfloat16 g_x_h[(size_t)NROWS * D_IN];
__device__ __nv_bfloat16 g_x_l[(size_t)NROWS * D_IN];
__device__ __nv_bfloat16 g_wb_h[256 * D_IN];
__device__ __nv_bfloat16 g_wb_l[256 * D_IN];

// ---------------- split helpers ----------------
__device__ __forceinline__ uint32_t pack_bf2(__nv_bfloat16 a, __nv_bfloat16 b) {
    return (uint32_t)__bfloat16_as_ushort(a) | ((uint32_t)__bfloat16_as_ushort(b) << 16);
}
__device__ __forceinline__ void split4(float4 v, uint2& hi, uint2& lo) {
    __nv_bfloat16 hx = __float2bfloat16_rn(v.x);
    __nv_bfloat16 hy = __float2bfloat16_rn(v.y);
    __nv_bfloat16 hz = __float2bfloat16_rn(v.z);
    __nv_bfloat16 hw = __float2bfloat16_rn(v.w);
    __nv_bfloat16 lx = __float2bfloat16_rn(v.x - __bfloat162float(hx));
    __nv_bfloat16 ly = __float2bfloat16_rn(v.y - __bfloat162float(hy));
    __nv_bfloat16 lz = __float2bfloat16_rn(v.z - __bfloat162float(hz));
    __nv_bfloat16 lw = __float2bfloat16_rn(v.w - __bfloat162float(hw));
    hi = make_uint2(pack_bf2(hx, hy), pack_bf2(hz, hw));
    lo = make_uint2(pack_bf2(lx, ly), pack_bf2(lz, lw));
}

#define N4Q (NROWS * LORA / 4)            // 3145728
#define N4X (NROWS * D_IN / 4)            // 14680064
#define N4B (256 * D_IN / 4)              // 458752
#define PREP_TOTAL (2 * N4Q + N4X + N4B)

// one kernel does all splits + the combined proj-weight build
__global__ void prep_all(const float4* __restrict__ qr, const float4* __restrict__ wqb,
                         const float4* __restrict__ x,
                         const float* __restrict__ wk, const float* __restrict__ wp)
{
    int i = blockIdx.x * blockDim.x + threadIdx.x;
    if (i >= PREP_TOTAL) return;
    if (i < N4Q) {
        uint2 h, l; split4(qr[i], h, l);
        ((uint2*)g_qr_h)[i] = h; ((uint2*)g_qr_l)[i] = l;
    } else if (i < 2 * N4Q) {
        int j = i - N4Q;
        uint2 h, l; split4(wqb[j], h, l);
        ((uint2*)g_wq_h)[j] = h; ((uint2*)g_wq_l)[j] = l;
    } else if (i < 2 * N4Q + N4X) {
        int j = i - 2 * N4Q;
        uint2 h, l; split4(x[j], h, l);
        ((uint2*)g_x_h)[j] = h; ((uint2*)g_x_l)[j] = l;
    } else {
        int j = i - 2 * N4Q - N4X;
        int row = j / (D_IN / 4);
        int c4  = j % (D_IN / 4);
        float4 v;
        if (row < 128)      v = ((const float4*)wk)[row * (D_IN / 4) + c4];
        else if (row < 192) {
            v = ((const float4*)wp)[(row - 128) * (D_IN / 4) + c4];
            v.x *= WSCALE; v.y *= WSCALE; v.z *= WSCALE; v.w *= WSCALE;
        } else v = make_float4(0.f, 0.f, 0.f, 0.f);
        uint2 h, l; split4(v, h, l);
        ((uint2*)g_wb_h)[j] = h; ((uint2*)g_wb_l)[j] = l;
    }
}

// ---------------- PTX helpers ----------------
__device__ __forceinline__ uint32_t elect_one_pred() {
    uint32_t p;
    asm volatile("{\n\t.reg .pred p;\n\telect.sync _|p, 0xFFFFFFFF;\n\tselp.b32 %0, 1, 0, p;\n\t}" : "=r"(p));
    return p;
}
__device__ __forceinline__ uint32_t smem_u32(const void* p) {
    uint32_t a;
    asm("{ .reg .u64 t; cvta.to.shared.u64 t, %1; cvt.u32.u64 %0, t; }" : "=r"(a) : "l"(p));
    return a;
}

#define MBARRIER_INIT(a, c) \
    asm volatile("mbarrier.init.shared.b64 [%0], %1;" :: "r"((uint32_t)(a)), "r"((uint32_t)(c)) : "memory")
#define MBARRIER_EXPECT_TX(a, b) \
    asm volatile("mbarrier.arrive.expect_tx.shared.b64 _, [%0], %1;" :: "r"((uint32_t)(a)), "r"((uint32_t)(b)) : "memory")

#define MBARRIER_WAIT_PARITY(mbar, par) do {                                          \
    uint32_t _m = (uint32_t)(mbar), _p = (uint32_t)(par), _d;                         \
    asm volatile("{\n\t.reg .pred p;\n\t"                                             \
        "mbarrier.try_wait.parity.acquire.cta.shared::cta.b64 p, [%1], %2;\n\t"       \
        "selp.b32 %0, 1, 0, p;\n\t}" : "=r"(_d) : "r"(_m), "r"(_p) : "memory");       \
    if (!_d) {                                                                         \
        asm volatile("{\n\t.reg .pred P1;\n\t"                                        \
            "WL_%=:\n\t"                                                              \
            "mbarrier.try_wait.parity.acquire.cta.shared::cta.b64 P1, [%0], %1, 0x989680;\n\t" \
            "@P1 bra.uni WD_%=;\n\t"                                                  \
            "bra.uni WL_%=;\n\t"                                                      \
            "WD_%=:\n\t}" :: "r"(_m), "r"(_p) : "memory");                            \
    }                                                                                  \
} while (0)

#define TMA_LOAD_3D(sa, tm, cx, cy, cz, mb)                                           \
    asm volatile("cp.async.bulk.tensor.3d.shared::cta.global.tile.mbarrier::complete_tx::bytes " \
        "[%0], [%1, {%2, %3, %4}], [%5];"                                             \
        :: "r"((uint32_t)(sa)), "l"(tm), "r"((int)(cx)), "r"((int)(cy)), "r"((int)(cz)), \
           "r"((uint32_t)(mb)) : "memory")

#define FENCE_PROXY_ASYNC() asm volatile("fence.proxy.async.shared::cta;" ::: "memory")

#define LDSM4(r0, r1, r2, r3, addr)                                              \
    asm volatile("ldmatrix.sync.aligned.m8n8.x4.shared.b16 {%0,%1,%2,%3},[%4];"  \
                 : "=r"(r0), "=r"(r1), "=r"(r2), "=r"(r3) : "r"(addr))

#define MMA_BF16(d, a, b)                                                        \
    asm volatile("mma.sync.aligned.m16n8k16.row.col.f32.bf16.bf16.f32 "          \
                 "{%0,%1,%2,%3},{%4,%5,%6,%7},{%8,%9},{%0,%1,%2,%3};"            \
                 : "+f"((d)[0]), "+f"((d)[1]), "+f"((d)[2]), "+f"((d)[3])        \
                 : "r"((a)[0]), "r"((a)[1]), "r"((a)[2]), "r"((a)[3]),           \
                   "r"((b)[0]), "r"((b)[1]))

// SW128 swizzle: XOR bits [9:7] into bits [6:4] (row stride = 128 B)
__device__ __forceinline__ uint32_t swz(uint32_t o) { return o ^ ((o >> 3) & 0x70); }

// ---------------- smem layout ----------------
#define CTRL     1024
#define STAGE_B  65536         // AH 16K | AL 16K | BH 16K | BL 16K  (128 rows x 128B)
#define AH_O     0
#define AL_O     16384
#define BH_O     32768
#define BL_O     49152
#define NSTAGE   3
#define SMEM_TOT (CTRL + NSTAGE * STAGE_B)   // 197632

// =====================================================================
// Unified TMA-fed mma.sync GEMM + fused epilogues.
//   bid <  128 : proj  (A = x splits, B = wb splits, K = 7168)
//                 bn==0 tile -> LayerNorm+RoPE+FWHT -> kout
//                 bn==1 tile -> weights (cols 0..63) -> wout
//   bid >= 128 : q     (A = qr splits, B = wq splits, K = 1536)
//                 RoPE+FWHT -> qout
// 256 threads, warp grid 2x4, warp tile 64x32, K-chunk 64, 3-stage TMA.
// =====================================================================
__global__ __launch_bounds__(256, 1)
void fused_gemm(const __grid_constant__ CUtensorMap mQAh, const __grid_constant__ CUtensorMap mQAl,
                const __grid_constant__ CUtensorMap mQBh, const __grid_constant__ CUtensorMap mQBl,
                const __grid_constant__ CUtensorMap mPAh, const __grid_constant__ CUtensorMap mPAl,
                const __grid_constant__ CUtensorMap mPBh, const __grid_constant__ CUtensorMap mPBl,
                float* __restrict__ qout, float* __restrict__ kout, float* __restrict__ wout,
                const float* __restrict__ fc, const float* __restrict__ fs,
                const float* __restrict__ kg, const float* __restrict__ kb)
{
    extern __shared__ char smem_raw[];
    const uint32_t sb = smem_u32(smem_raw);
    const int tid = threadIdx.x, lane = tid & 31, warp = tid >> 5;
    const int wm = warp >> 2, wn = warp & 3;
    const int tm = wm << 6, tn = wn << 5;

    const int bid = blockIdx.x;
    const bool proj = (bid < 128);
    int bm, bn, K;
    const CUtensorMap *pAh, *pAl, *pBh, *pBl;
    if (proj) {
        bm = bid >> 1; bn = bid & 1; K = D_IN;
        pAh = &mPAh; pAl = &mPAl; pBh = &mPBh; pBl = &mPBl;
    } else {
        int t = bid - 128;
        bm = t & 63; bn = t >> 6; K = LORA;
        pAh = &mQAh; pAl = &mQAl; pBh = &mQBh; pBl = &mQBl;
    }
    const int niter = K >> 6;

    if (tid == 0) {
        MBARRIER_INIT(sb + 0, 1);
        MBARRIER_INIT(sb + 8, 1);
        MBARRIER_INIT(sb + 16, 1);
        FENCE_PROXY_ASYNC();
    }
    __syncthreads();

    const bool producer = (warp == 0) && elect_one_pred();

    // prologue: fill all 3 stages
    if (producer) {
        #pragma unroll
        for (int p = 0; p < NSTAGE; ++p) {
            const uint32_t fb = sb + p * 8;
            MBARRIER_EXPECT_TX(fb, STAGE_B);
            const uint32_t tb = sb + CTRL + p * STAGE_B;
            const int kt = p << 6;
            TMA_LOAD_3D(tb + AH_O, pAh, kt, bm * 128, 0, fb);
            TMA_LOAD_3D(tb + AL_O, pAl, kt, bm * 128, 0, fb);
            TMA_LOAD_3D(tb + BH_O, pBh, kt, bn * 128, 0, fb);
            TMA_LOAD_3D(tb + BL_O, pBl, kt, bn * 128, 0, fb);
        }
    }

    float acc[4][4][4] = {};
    int fph[NSTAGE] = {0, 0, 0};

    for (int it = 0; it < niter; ++it) {
        const int s = (it % NSTAGE);
        MBARRIER_WAIT_PARITY(sb + s * 8, fph[s]);
        fph[s] ^= 1;
        const uint32_t tb = sb + CTRL + s * STAGE_B;

        #pragma unroll
        for (int s2 = 0; s2 < 4; ++s2) {
            const uint32_t kbyte = s2 << 5;
            // B fragments hi & lo (4 n-tiles each)
            uint32_t bhf[4][2], blf[4][2];
            {
                const int g = lane >> 3;
                #pragma unroll
                for (int p = 0; p < 2; ++p) {
                    const int row = tn + (((p << 1) + (g >> 1)) << 3) + (lane & 7);
                    const uint32_t off = swz(row * 128 + kbyte + ((g & 1) << 4));
                    LDSM4(bhf[2*p][0], bhf[2*p][1], bhf[2*p+1][0], bhf[2*p+1][1], tb + BH_O + off);
                    LDSM4(blf[2*p][0], blf[2*p][1], blf[2*p+1][0], blf[2*p+1][1], tb + BL_O + off);
                }
            }
            uint32_t a[4][4];
            #pragma unroll
            for (int i = 0; i < 4; ++i) {
                const int row = tm + (i << 4) + (lane & 15);
                const uint32_t off = swz(row * 128 + kbyte + ((lane >> 4) << 4));
                LDSM4(a[i][0], a[i][1], a[i][2], a[i][3], tb + AH_O + off);
            }
            #pragma unroll
            for (int i = 0; i < 4; ++i)
                #pragma unroll
                for (int j = 0; j < 4; ++j) {
                    MMA_BF16(acc[i][j], a[i], bhf[j]);
                    MMA_BF16(acc[i][j], a[i], blf[j]);
                }
            #pragma unroll
            for (int i = 0; i < 4; ++i) {
                const int row = tm + (i << 4) + (lane & 15);
                const uint32_t off = swz(row * 128 + kbyte + ((lane >> 4) << 4));
                LDSM4(a[i][0], a[i][1], a[i][2], a[i][3], tb + AL_O + off);
            }
            #pragma unroll
            for (int i = 0; i < 4; ++i)
                #pragma unroll
                for (int j = 0; j < 4; ++j)
                    MMA_BF16(acc[i][j], a[i], bhf[j]);
        }

        __syncthreads();
        if (producer && it + NSTAGE < niter) {
            const uint32_t fb = sb + s * 8;
            MBARRIER_EXPECT_TX(fb, STAGE_B);
            const int kt = (it + NSTAGE) << 6;
            TMA_LOAD_3D(tb + AH_O, pAh, kt, bm * 128, 0, fb);
            TMA_LOAD_3D(tb + AL_O, pAl, kt, bm * 128, 0, fb);
            TMA_LOAD_3D(tb + BH_O, pBh, kt, bn * 128, 0, fb);
            TMA_LOAD_3D(tb + BL_O, pBl, kt, bn * 128, 0, fb);
        }
    }

    // ================= fused epilogue =================
    if (proj && bn == 1) {
        // weights: cols 0..63 valid (WSCALE already folded into wb)
        if (wn < 2) {
            #pragma unroll
            for (int i = 0; i < 4; ++i)
                #pragma unroll
                for (int j = 0; j < 4; ++j) {
                    const int gm = bm * 128 + tm + (i << 4) + (lane >> 2);
                    const int gn = tn + (j << 3) + ((lane & 3) << 1);
                    *(float2*)(wout + (size_t)gm * 64 + gn) =
                        make_float2(acc[i][j][0], acc[i][j][1]);
                    *(float2*)(wout + (size_t)(gm + 8) * 64 + gn) =
                        make_float2(acc[i][j][2], acc[i][j][3]);
                }
        }
        return;
    }

    // stage smem is free now (all stages consumed, nothing in flight)
    __syncthreads();
    float* tile = reinterpret_cast<float*>(smem_raw + CTRL);   // [128][132]
    #pragma unroll
    for (int i = 0; i < 4; ++i)
        #pragma unroll
        for (int j = 0; j < 4; ++j) {
            const int r0 = tm + (i << 4) + (lane >> 2);
            const int c0 = tn + (j << 3) + ((lane & 3) << 1);
            tile[r0 * 132 + c0]           = acc[i][j][0];
            tile[r0 * 132 + c0 + 1]       = acc[i][j][1];
            tile[(r0 + 8) * 132 + c0]     = acc[i][j][2];
            tile[(r0 + 8) * 132 + c0 + 1] = acc[i][j][3];
        }
    __syncthreads();

    // each warp transforms 16 rows; full warp per row (shuffle FWHT)
    const float gv = proj ? kg[lane] : 0.f;  // unused for q
    for (int rr = 0; rr < 16; ++rr) {
        const int row = warp * 16 + rr;
        const int grow = bm * 128 + row;
        const float* tr = tile + row * 132;
        float v0 = tr[lane], v1 = tr[lane + 32], v2 = tr[lane + 64], v3 = tr[lane + 96];

        if (proj) {
            // layernorm over 128
            float sum = v0 + v1 + v2 + v3;
            float sq  = v0*v0 + v1*v1 + v2*v2 + v3*v3;
            #pragma unroll
            for (int o = 16; o; o >>= 1) {
                sum += __shfl_xor_sync(0xffffffffu, sum, o);
                sq  += __shfl_xor_sync(0xffffffffu, sq,  o);
            }
            const float mu  = sum * (1.f / 128.f);
            const float var = sq * (1.f / 128.f) - mu * mu;
            const float r   = rsqrtf(var + 1e-5f);
            v0 = (v0 - mu) * r * gv          + kb[lane];
            v1 = (v1 - mu) * r * kg[lane+32] + kb[lane + 32];
            v2 = (v2 - mu) * r * kg[lane+64] + kb[lane + 64];
            v3 = (v3 - mu) * r * kg[lane+96] + kb[lane + 96];
        }

        // RoPE on dims 0..63, pairs (lane, lane+32)
        const int pos = grow & (S_LEN - 1);
        const float c = fc[pos * 32 + lane];
        const float s = fs[pos * 32 + lane];
        const float x1 = v0, x2 = v1;
        v0 = x1 * c - x2 * s;
        v1 = x1 * s + x2 * c;

        // FWHT (== @Hmat, Sylvester) + scale
        #pragma unroll
        for (int st = 1; st < 32; st <<= 1) {
            float p0 = __shfl_xor_sync(0xffffffffu, v0, st);
            float p1 = __shfl_xor_sync(0xffffffffu, v1, st);
            float p2 = __shfl_xor_sync(0xffffffffu, v2, st);
            float p3 = __shfl_xor_sync(0xffffffffu, v3, st);
            if (lane & st) { v0 = p0 - v0; v1 = p1 - v1; v2 = p2 - v2; v3 = p3 - v3; }
            else           { v0 += p0;     v1 += p1;     v2 += p2;     v3 += p3;     }
        }
        float t0 = v0 + v1, t1 = v0 - v1, t2 = v2 + v3, t3 = v2 - v3;
        v0 = t0 + t2; v2 = t0 - t2; v1 = t1 + t3; v3 = t1 - t3;

        if (proj) {
            float* ob = kout + (size_t)grow * 128;
            ob[lane]      = v0 * HSCALE;
            ob[lane + 32] = v1 * HSCALE;
            ob[lane + 64] = v2 * HSCALE;
            ob[lane + 96] = v3 * HSCALE;
        } else {
            float* ob = qout + (size_t)grow * 8192 + bn * 128;
            ob[lane]      = v0 * HSCALE;
            ob[lane + 32] = v1 * HSCALE;
            ob[lane + 64] = v2 * HSCALE;
            ob[lane + 96] = v3 * HSCALE;
        }
    }
}

__global__ void write_end(float* __restrict__ eout, const int* __restrict__ sp)
{
    *eout = (float)(*sp + S_LEN);
}

// =====================================================================
typedef CUresult (*EncodeFn)(CUtensorMap*, CUtensorMapDataType, cuuint32_t, void*,
                             const cuuint64_t*, const cuuint64_t*, const cuuint32_t*,
                             const cuuint32_t*, CUtensorMapInterleave, CUtensorMapSwizzle,
                             CUtensorMapL2promotion, CUtensorMapFloatOOBfill);

static void make_map(EncodeFn enc, CUtensorMap* m, void* base, int K, int R)
{
    cuuint64_t dims[3]    = {(cuuint64_t)K, (cuuint64_t)R, 1};
    cuuint64_t strides[2] = {(cuuint64_t)K * 2, (cuuint64_t)K * 2 * (cuuint64_t)R};
    cuuint32_t box[3]     = {64, 128, 1};
    cuuint32_t es[3]      = {1, 1, 1};
    enc(m, CU_TENSOR_MAP_DATA_TYPE_BFLOAT16, 3, base, dims, strides, box, es,
        CU_TENSOR_MAP_INTERLEAVE_NONE, CU_TENSOR_MAP_SWIZZLE_128B,
        CU_TENSOR_MAP_L2_PROMOTION_L2_128B, CU_TENSOR_MAP_FLOAT_OOB_FILL_NONE);
}

extern "C" void kernel_launch(void* const* d_in, const int* in_sizes, int n_in,
                              void* d_out, int out_size)
{
    const float* x   = (const float*)d_in[0];
    const float* qr  = (const float*)d_in[1];
    const float* fc  = (const float*)d_in[2];
    const float* fs  = (const float*)d_in[3];
    const float* wqb = (const float*)d_in[4];
    const float* wk  = (const float*)d_in[5];
    const float* kg  = (const float*)d_in[6];
    const float* kb  = (const float*)d_in[7];
    const float* wp  = (const float*)d_in[8];
    const int*   sp  = (const int*)d_in[9];

    float* out  = (float*)d_out;
    float* qout = out;
    float* wout = out + QN;
    float* kout = out + QN + WN;
    float* eout = out + QN + WN + KN;

    void *qrh, *qrl, *wqh, *wql, *xh, *xl, *wbh, *wbl;
    cudaGetSymbolAddress(&qrh, g_qr_h);
    cudaGetSymbolAddress(&qrl, g_qr_l);
    cudaGetSymbolAddress(&wqh, g_wq_h);
    cudaGetSymbolAddress(&wql, g_wq_l);
    cudaGetSymbolAddress(&xh,  g_x_h);
    cudaGetSymbolAddress(&xl,  g_x_l);
    cudaGetSymbolAddress(&wbh, g_wb_h);
    cudaGetSymbolAddress(&wbl, g_wb_l);

    EncodeFn enc = nullptr;
    cudaDriverEntryPointQueryResult qres;
    cudaGetDriverEntryPoint("cuTensorMapEncodeTiled", (void**)&enc, cudaEnableDefault, &qres);

    CUtensorMap mQAh, mQAl, mQBh, mQBl, mPAh, mPAl, mPBh, mPBl;
    make_map(enc, &mQAh, qrh, LORA, NROWS);
    make_map(enc, &mQAl, qrl, LORA, NROWS);
    make_map(enc, &mQBh, wqh, LORA, NROWS);
    make_map(enc, &mQBl, wql, LORA, NROWS);
    make_map(enc, &mPAh, xh,  D_IN, NROWS);
    make_map(enc, &mPAl, xl,  D_IN, NROWS);
    make_map(enc, &mPBh, wbh, D_IN, 256);
    make_map(enc, &mPBl, wbl, D_IN, 256);

    cudaFuncSetAttribute(fused_gemm, cudaFuncAttributeMaxDynamicSharedMemorySize, SMEM_TOT);

    prep_all<<<(PREP_TOTAL + 255) / 256, 256>>>(
        (const float4*)qr, (const float4*)wqb, (const float4*)x, wk, wp);

    fused_gemm<<<4224, 256, SMEM_TOT>>>(
        mQAh, mQAl, mQBh, mQBl, mPAh, mPAl, mPBh, mPBl,
        qout, kout, wout, fc, fs, kg, kb);

    write_end<<<1, 1>>>(eout, sp);
}